// round 11
// baseline (speedup 1.0000x reference)
#include <cuda_runtime.h>
#include <cuda_fp16.h>
#include <cstdint>

#define NB 16
#define NS 2048
#define ND 64
#define NO 128
#define KSPLIT 16
#define KC 128            // K per g1 block

// ---------------- scratch (no allocs allowed) ------------------------------
__device__ float  g_Ypart[KSPLIT * NB * NO * ND];   // 8 MB fp32 partials
__device__ __half g_yh[NB * NO * ND];               // Y fp16 [b][o][d]
__device__ __half g_xh[NB * NS * ND];               // x fp16, layout = x
__device__ __half g_wh[NO * NS];                    // W fp16, layout = W

// ---------------- helpers --------------------------------------------------
__device__ __forceinline__ uint32_t smem_u32(const void* p) {
    uint32_t a;
    asm("{ .reg .u64 t; cvta.to.shared.u64 t, %1; cvt.u32.u64 %0, t; }"
        : "=r"(a) : "l"(p));
    return a;
}
__device__ __forceinline__ void ldm_x4(uint32_t* r, uint32_t addr) {
    asm volatile("ldmatrix.sync.aligned.m8n8.x4.shared.b16 {%0,%1,%2,%3}, [%4];"
                 : "=r"(r[0]), "=r"(r[1]), "=r"(r[2]), "=r"(r[3]) : "r"(addr));
}
__device__ __forceinline__ void ldm_x4t(uint32_t* r, uint32_t addr) {
    asm volatile("ldmatrix.sync.aligned.m8n8.x4.trans.shared.b16 {%0,%1,%2,%3}, [%4];"
                 : "=r"(r[0]), "=r"(r[1]), "=r"(r[2]), "=r"(r[3]) : "r"(addr));
}
__device__ __forceinline__ void mma_f16(float* c, const uint32_t* a,
                                        const uint32_t* b) {
    asm volatile(
        "mma.sync.aligned.m16n8k16.row.col.f32.f16.f16.f32 "
        "{%0,%1,%2,%3}, {%4,%5,%6,%7}, {%8,%9}, {%0,%1,%2,%3};"
        : "+f"(c[0]), "+f"(c[1]), "+f"(c[2]), "+f"(c[3])
        : "r"(a[0]), "r"(a[1]), "r"(a[2]), "r"(a[3]), "r"(b[0]), "r"(b[1]));
}
__device__ __forceinline__ void cp_async16(uint32_t saddr, const void* g) {
    asm volatile("cp.async.cg.shared.global [%0], [%1], 16;"
                 :: "r"(saddr), "l"(g) : "memory");
}
#define CP_COMMIT() asm volatile("cp.async.commit_group;" ::: "memory")
#define CP_WAIT0()  asm volatile("cp.async.wait_group 0;" ::: "memory")

__device__ __forceinline__ uint32_t hpack2(float a, float b) {
    __half2 h = __floats2half2_rn(a, b);
    return *(uint32_t*)&h;
}

// ===========================================================================
// prep: layout-preserving fp32 -> fp16 of x and W.
// blocks 0..511 -> x (524288 float4), 512..575 -> W (65536 float4).
// ===========================================================================
__global__ __launch_bounds__(256) void prep(const float* __restrict__ x,
                                            const float* __restrict__ W) {
    const int bid = blockIdx.x;
    const float4* src;
    uint2* dst;
    size_t base;
    if (bid < 512) {
        src = (const float4*)x;  dst = (uint2*)g_xh;  base = (size_t)bid * 1024;
    } else {
        src = (const float4*)W;  dst = (uint2*)g_wh;  base = (size_t)(bid - 512) * 1024;
    }
#pragma unroll
    for (int j = 0; j < 4; j++) {
        size_t e = base + threadIdx.x + j * 256;
        float4 v = src[e];
        dst[e] = make_uint2(hpack2(v.x, v.y), hpack2(v.z, v.w));
    }
}

// ===========================================================================
// G1: Ypart[ks][b][o=128][d=64] = W[o, kslice] @ x[b, kslice, d]
// 1-term fp16, pure cp.async fp16 loads. grid (KSPLIT=16, NB) = 256 CTAs,
// 256 thr (8 warps 4x2), K=128 per CTA.
// smem: WA [128 o][pitch 272B], XB [128 k][pitch 144B]. 52KB.
// ===========================================================================
#define G1_WAHI 0
#define G1_XBHI 34816
#define G1_SMEM 53248

__global__ __launch_bounds__(256, 3) void g1() {
    extern __shared__ char sm[];
    const int tid = threadIdx.x, wid = tid >> 5, lane = tid & 31;
    const int ks = blockIdx.x, b = blockIdx.y;
    const int wm = wid & 3, wn = wid >> 2;
    const int o0 = wm * 32, d0 = wn * 32;
    const int kbase = ks * KC;

    const uint32_t s_wahi = smem_u32(sm + G1_WAHI);
    const uint32_t s_xbhi = smem_u32(sm + G1_XBHI);

    // W tile: 128 o x 16 chunks (16B = 8 fp16)
#pragma unroll
    for (int j = 0; j < 8; j++) {
        int idx = tid + j * 256;
        int o = idx >> 4, c = idx & 15;
        cp_async16(s_wahi + o * 272 + c * 16, &g_wh[(size_t)o * NS + kbase + c * 8]);
    }
    // x tile: 128 k x 8 chunks
#pragma unroll
    for (int j = 0; j < 4; j++) {
        int idx = tid + j * 256;
        int k = idx >> 3, c = idx & 7;
        cp_async16(s_xbhi + k * 144 + c * 16,
                   &g_xh[((size_t)b * NS + kbase + k) * ND + c * 8]);
    }
    CP_COMMIT();
    CP_WAIT0();
    __syncthreads();

    float acc[2][4][4];
#pragma unroll
    for (int mt = 0; mt < 2; mt++)
#pragma unroll
        for (int nt = 0; nt < 4; nt++)
#pragma unroll
            for (int q = 0; q < 4; q++) acc[mt][nt][q] = 0.f;

#pragma unroll
    for (int kk = 0; kk < 8; kk++) {
        uint32_t ahi[2][4];
#pragma unroll
        for (int mt = 0; mt < 2; mt++) {
            uint32_t off = (uint32_t)((o0 + mt * 16 + (lane & 15)) * 272 +
                                      kk * 32 + (lane >> 4) * 16);
            ldm_x4(ahi[mt], s_wahi + off);
        }
        uint32_t bhi[2][4];
#pragma unroll
        for (int p = 0; p < 2; p++) {
            uint32_t off = (uint32_t)((kk * 16 + (lane & 15)) * 144 +
                                      (d0 + p * 16 + (lane >> 4) * 8) * 2);
            ldm_x4t(bhi[p], s_xbhi + off);
        }
#pragma unroll
        for (int mt = 0; mt < 2; mt++)
#pragma unroll
            for (int nt = 0; nt < 4; nt++)
                mma_f16(acc[mt][nt], ahi[mt], &bhi[nt >> 1][(nt & 1) * 2]);
    }

    // epilogue -> Ypart fp32
    float* Yp = g_Ypart + ((size_t)(ks * NB + b) * NO) * ND;
#pragma unroll
    for (int mt = 0; mt < 2; mt++)
#pragma unroll
        for (int nt = 0; nt < 4; nt++) {
            int o = o0 + mt * 16 + (lane >> 2);
            int d = d0 + nt * 8 + (lane & 3) * 2;
            float* p = Yp + (size_t)o * ND + d;
            *(float2*)p = make_float2(acc[mt][nt][0], acc[mt][nt][1]);
            *(float2*)(p + 8 * ND) = make_float2(acc[mt][nt][2], acc[mt][nt][3]);
        }
}

// ===========================================================================
// Reduce 16 partials -> Y fp16
// ===========================================================================
__global__ __launch_bounds__(128) void yred() {
    int e = blockIdx.x * 128 + threadIdx.x;   // float4 idx, 32768 total
    const float4* src = (const float4*)g_Ypart;
    const int stride = NB * NO * ND / 4;
    float4 s = src[e];
#pragma unroll
    for (int p = 1; p < KSPLIT; p++) {
        float4 v = src[(size_t)p * stride + e];
        s.x += v.x; s.y += v.y; s.z += v.z; s.w += v.w;
    }
    *(uint2*)&g_yh[e * 4] = make_uint2(hpack2(s.x, s.y), hpack2(s.z, s.w));
}

// ===========================================================================
// G2: out[b][s][o] = x[b,s,:] . Y[b,o,:] + bias[o]
// 1-term fp16, pure cp.async fp16 loads. grid (NS/64, NB) = 512 blocks,
// 256 thr (8 warps: 4 s x 2 o). Tile M=64 s, N=128 o, K=64. smem 28KB.
// ===========================================================================
#define G2_XHI 0
#define G2_YHI 9216
#define G2_BIAS 27648
#define G2_SMEM 28160

__global__ __launch_bounds__(256, 3) void g2(const float* __restrict__ bias,
                                             float* __restrict__ out) {
    extern __shared__ char sm[];
    float* bias_s = (float*)(sm + G2_BIAS);
    const int tid = threadIdx.x, wid = tid >> 5, lane = tid & 31;
    const int st = blockIdx.x, b = blockIdx.y;
    const int s0 = st * 64;
    const int wm = wid & 3, wn = wid >> 2;
    const int s0w = wm * 16, o0w = wn * 64;

    const uint32_t s_xhi = smem_u32(sm + G2_XHI);
    const uint32_t s_yhi = smem_u32(sm + G2_YHI);

    // Y tile: 128 o x 8 chunks
#pragma unroll
    for (int j = 0; j < 4; j++) {
        int idx = tid + j * 256;
        int o = idx >> 3, c = idx & 7;
        cp_async16(s_yhi + o * 144 + c * 16, &g_yh[(size_t)(b * NO + o) * ND + c * 8]);
    }
    // X tile: 64 s x 8 chunks
#pragma unroll
    for (int j = 0; j < 2; j++) {
        int idx = tid + j * 256;
        int s = idx >> 3, c = idx & 7;
        cp_async16(s_xhi + s * 144 + c * 16,
                   &g_xh[((size_t)b * NS + s0 + s) * ND + c * 8]);
    }
    if (tid < NO) bias_s[tid] = bias[tid];
    CP_COMMIT();
    CP_WAIT0();
    __syncthreads();

    float acc[8][4];
#pragma unroll
    for (int nt = 0; nt < 8; nt++)
#pragma unroll
        for (int q = 0; q < 4; q++) acc[nt][q] = 0.f;

#pragma unroll
    for (int kk = 0; kk < 4; kk++) {
        uint32_t ahi[4];
        {
            uint32_t off = (uint32_t)((s0w + (lane & 15)) * 144 + kk * 32 +
                                      (lane >> 4) * 16);
            ldm_x4(ahi, s_xhi + off);
        }
        uint32_t bhi[4][4];
#pragma unroll
        for (int p = 0; p < 4; p++) {
            uint32_t off = (uint32_t)((o0w + p * 16 + (lane >> 4) * 8 + (lane & 7)) * 144 +
                                      kk * 32 + ((lane >> 3) & 1) * 16);
            ldm_x4(bhi[p], s_yhi + off);
        }
#pragma unroll
        for (int nt = 0; nt < 8; nt++)
            mma_f16(acc[nt], ahi, &bhi[nt >> 1][(nt & 1) * 2]);
    }

    // epilogue: +bias -> out
    const int srow = s0 + s0w + (lane >> 2);
#pragma unroll
    for (int nt = 0; nt < 8; nt++) {
        int o = o0w + nt * 8 + (lane & 3) * 2;
        float2 bb = *(float2*)&bias_s[o];
        float* p0 = out + ((size_t)b * NS + srow) * NO + o;
        *(float2*)p0 = make_float2(acc[nt][0] + bb.x, acc[nt][1] + bb.y);
        *(float2*)(p0 + 8 * NO) = make_float2(acc[nt][2] + bb.x, acc[nt][3] + bb.y);
    }
}

// ===========================================================================
extern "C" void kernel_launch(void* const* d_in, const int* in_sizes, int n_in,
                              void* d_out, int out_size) {
    const float* x = nullptr;
    const float* W = nullptr;
    const float* bias = nullptr;
    for (int i = 0; i < n_in; i++) {
        if (in_sizes[i] == NB * NS * ND)      x = (const float*)d_in[i];
        else if (in_sizes[i] == NO * NS)      W = (const float*)d_in[i];
        else if (in_sizes[i] == NO)           bias = (const float*)d_in[i];
    }
    float* out = (float*)d_out;

    cudaFuncSetAttribute(g1, cudaFuncAttributeMaxDynamicSharedMemorySize, G1_SMEM);
    cudaFuncSetAttribute(g2, cudaFuncAttributeMaxDynamicSharedMemorySize, G2_SMEM);

    prep<<<576, 256>>>(x, W);
    g1<<<dim3(KSPLIT, NB), 256, G1_SMEM>>>();
    yred<<<(NB * NO * ND / 4) / 128, 128>>>();
    g2<<<dim3(NS / 64, NB), 256, G2_SMEM>>>(bias, out);
}

// round 12
// speedup vs baseline: 1.0239x; 1.0239x over previous
#include <cuda_runtime.h>
#include <cuda_fp16.h>
#include <cstdint>

#define NB 16
#define NS 2048
#define ND 64
#define NO 128
#define KSPLIT 16
#define KC 128            // K per g1 block

// ---------------- scratch (no allocs allowed) ------------------------------
__device__ float  g_Ypart[KSPLIT * NB * NO * ND];   // 8 MB fp32 partials
__device__ __half g_yh[NB * NO * ND];               // Y fp16 [b][o][d]
__device__ __half g_xh[NB * NS * ND];               // x fp16, layout = x
__device__ __half g_wh[NO * NS];                    // W fp16, layout = W

// ---------------- helpers --------------------------------------------------
__device__ __forceinline__ uint32_t smem_u32(const void* p) {
    uint32_t a;
    asm("{ .reg .u64 t; cvta.to.shared.u64 t, %1; cvt.u32.u64 %0, t; }"
        : "=r"(a) : "l"(p));
    return a;
}
__device__ __forceinline__ void ldm_x4(uint32_t* r, uint32_t addr) {
    asm volatile("ldmatrix.sync.aligned.m8n8.x4.shared.b16 {%0,%1,%2,%3}, [%4];"
                 : "=r"(r[0]), "=r"(r[1]), "=r"(r[2]), "=r"(r[3]) : "r"(addr));
}
__device__ __forceinline__ void ldm_x4t(uint32_t* r, uint32_t addr) {
    asm volatile("ldmatrix.sync.aligned.m8n8.x4.trans.shared.b16 {%0,%1,%2,%3}, [%4];"
                 : "=r"(r[0]), "=r"(r[1]), "=r"(r[2]), "=r"(r[3]) : "r"(addr));
}
__device__ __forceinline__ void mma_f16(float* c, const uint32_t* a,
                                        const uint32_t* b) {
    asm volatile(
        "mma.sync.aligned.m16n8k16.row.col.f32.f16.f16.f32 "
        "{%0,%1,%2,%3}, {%4,%5,%6,%7}, {%8,%9}, {%0,%1,%2,%3};"
        : "+f"(c[0]), "+f"(c[1]), "+f"(c[2]), "+f"(c[3])
        : "r"(a[0]), "r"(a[1]), "r"(a[2]), "r"(a[3]), "r"(b[0]), "r"(b[1]));
}
__device__ __forceinline__ void cp_async16(uint32_t saddr, const void* g) {
    asm volatile("cp.async.cg.shared.global [%0], [%1], 16;"
                 :: "r"(saddr), "l"(g) : "memory");
}
#define CP_COMMIT() asm volatile("cp.async.commit_group;" ::: "memory")
#define CP_WAIT0()  asm volatile("cp.async.wait_group 0;" ::: "memory")

__device__ __forceinline__ uint32_t hpack2(float a, float b) {
    __half2 h = __floats2half2_rn(a, b);
    return *(uint32_t*)&h;
}

// ===========================================================================
// prep: layout-preserving fp32 -> fp16 of x and W.
// blocks 0..511 -> x (524288 float4), 512..575 -> W (65536 float4).
// ===========================================================================
__global__ __launch_bounds__(256) void prep(const float* __restrict__ x,
                                            const float* __restrict__ W) {
    const int bid = blockIdx.x;
    const float4* src;
    uint2* dst;
    size_t base;
    if (bid < 512) {
        src = (const float4*)x;  dst = (uint2*)g_xh;  base = (size_t)bid * 1024;
    } else {
        src = (const float4*)W;  dst = (uint2*)g_wh;  base = (size_t)(bid - 512) * 1024;
    }
#pragma unroll
    for (int j = 0; j < 4; j++) {
        size_t e = base + threadIdx.x + j * 256;
        float4 v = src[e];
        dst[e] = make_uint2(hpack2(v.x, v.y), hpack2(v.z, v.w));
    }
}

// ===========================================================================
// G1: Ypart[ks][b][o=128][d=64] = W[o, kslice] @ x[b, kslice, d]
// 1-term fp16, pure cp.async fp16 loads. grid (KSPLIT=16, NB) = 256 CTAs,
// 256 thr (8 warps 4x2), K=128 per CTA. smem 52KB, 3 CTAs/SM.
// ===========================================================================
#define G1_WAHI 0
#define G1_XBHI 34816
#define G1_SMEM 53248

__global__ __launch_bounds__(256, 3) void g1() {
    extern __shared__ char sm[];
    const int tid = threadIdx.x, wid = tid >> 5, lane = tid & 31;
    const int ks = blockIdx.x, b = blockIdx.y;
    const int wm = wid & 3, wn = wid >> 2;
    const int o0 = wm * 32, d0 = wn * 32;
    const int kbase = ks * KC;

    const uint32_t s_wahi = smem_u32(sm + G1_WAHI);
    const uint32_t s_xbhi = smem_u32(sm + G1_XBHI);

    // W tile: 128 o x 16 chunks (16B = 8 fp16)
#pragma unroll
    for (int j = 0; j < 8; j++) {
        int idx = tid + j * 256;
        int o = idx >> 4, c = idx & 15;
        cp_async16(s_wahi + o * 272 + c * 16, &g_wh[(size_t)o * NS + kbase + c * 8]);
    }
    // x tile: 128 k x 8 chunks
#pragma unroll
    for (int j = 0; j < 4; j++) {
        int idx = tid + j * 256;
        int k = idx >> 3, c = idx & 7;
        cp_async16(s_xbhi + k * 144 + c * 16,
                   &g_xh[((size_t)b * NS + kbase + k) * ND + c * 8]);
    }
    CP_COMMIT();
    CP_WAIT0();
    __syncthreads();

    float acc[2][4][4];
#pragma unroll
    for (int mt = 0; mt < 2; mt++)
#pragma unroll
        for (int nt = 0; nt < 4; nt++)
#pragma unroll
            for (int q = 0; q < 4; q++) acc[mt][nt][q] = 0.f;

#pragma unroll
    for (int kk = 0; kk < 8; kk++) {
        uint32_t ahi[2][4];
#pragma unroll
        for (int mt = 0; mt < 2; mt++) {
            uint32_t off = (uint32_t)((o0 + mt * 16 + (lane & 15)) * 272 +
                                      kk * 32 + (lane >> 4) * 16);
            ldm_x4(ahi[mt], s_wahi + off);
        }
        uint32_t bhi[2][4];
#pragma unroll
        for (int p = 0; p < 2; p++) {
            uint32_t off = (uint32_t)((kk * 16 + (lane & 15)) * 144 +
                                      (d0 + p * 16 + (lane >> 4) * 8) * 2);
            ldm_x4t(bhi[p], s_xbhi + off);
        }
#pragma unroll
        for (int mt = 0; mt < 2; mt++)
#pragma unroll
            for (int nt = 0; nt < 4; nt++)
                mma_f16(acc[mt][nt], ahi[mt], &bhi[nt >> 1][(nt & 1) * 2]);
    }

    // epilogue -> Ypart fp32
    float* Yp = g_Ypart + ((size_t)(ks * NB + b) * NO) * ND;
#pragma unroll
    for (int mt = 0; mt < 2; mt++)
#pragma unroll
        for (int nt = 0; nt < 4; nt++) {
            int o = o0 + mt * 16 + (lane >> 2);
            int d = d0 + nt * 8 + (lane & 3) * 2;
            float* p = Yp + (size_t)o * ND + d;
            *(float2*)p = make_float2(acc[mt][nt][0], acc[mt][nt][1]);
            *(float2*)(p + 8 * ND) = make_float2(acc[mt][nt][2], acc[mt][nt][3]);
        }
}

// ===========================================================================
// Reduce 16 partials -> Y fp16
// ===========================================================================
__global__ __launch_bounds__(128) void yred() {
    int e = blockIdx.x * 128 + threadIdx.x;   // float4 idx, 32768 total
    const float4* src = (const float4*)g_Ypart;
    const int stride = NB * NO * ND / 4;
    float4 s = src[e];
#pragma unroll
    for (int p = 1; p < KSPLIT; p++) {
        float4 v = src[(size_t)p * stride + e];
        s.x += v.x; s.y += v.y; s.z += v.z; s.w += v.w;
    }
    *(uint2*)&g_yh[e * 4] = make_uint2(hpack2(s.x, s.y), hpack2(s.z, s.w));
}

// ===========================================================================
// G2: out[b][s][o] = x[b,s,:] . Y[b,o,:] + bias[o]
// 1-term fp16. Tile M=128 s, N=128 o, K=64.
// grid (NS/128, NB) = 256 CTAs, 256 thr (8 warps: 4 s x 2 o, each warp
// 2 m-tiles x 8 n-tiles = 64 mma). 2 CTAs/SM, ALL CTAs resident in 1 wave.
// smem: XS [128][144], YS [128][144], bias. 37KB.
// ===========================================================================
#define G2_XHI 0
#define G2_YHI 18432
#define G2_BIAS 36864
#define G2_SMEM 37376

__global__ __launch_bounds__(256, 2) void g2(const float* __restrict__ bias,
                                             float* __restrict__ out) {
    extern __shared__ char sm[];
    float* bias_s = (float*)(sm + G2_BIAS);
    const int tid = threadIdx.x, wid = tid >> 5, lane = tid & 31;
    const int st = blockIdx.x, b = blockIdx.y;
    const int s0 = st * 128;
    const int wm = wid & 3, wn = wid >> 2;
    const int s0w = wm * 16, o0w = wn * 64;   // m-tiles at s0w and s0w+64

    const uint32_t s_xhi = smem_u32(sm + G2_XHI);
    const uint32_t s_yhi = smem_u32(sm + G2_YHI);

    // Y tile: 128 o x 8 chunks
#pragma unroll
    for (int j = 0; j < 4; j++) {
        int idx = tid + j * 256;
        int o = idx >> 3, c = idx & 7;
        cp_async16(s_yhi + o * 144 + c * 16, &g_yh[(size_t)(b * NO + o) * ND + c * 8]);
    }
    // X tile: 128 s x 8 chunks
#pragma unroll
    for (int j = 0; j < 4; j++) {
        int idx = tid + j * 256;
        int s = idx >> 3, c = idx & 7;
        cp_async16(s_xhi + s * 144 + c * 16,
                   &g_xh[((size_t)b * NS + s0 + s) * ND + c * 8]);
    }
    if (tid < NO) bias_s[tid] = bias[tid];
    CP_COMMIT();
    CP_WAIT0();
    __syncthreads();

    float acc[2][8][4];
#pragma unroll
    for (int mt = 0; mt < 2; mt++)
#pragma unroll
        for (int nt = 0; nt < 8; nt++)
#pragma unroll
            for (int q = 0; q < 4; q++) acc[mt][nt][q] = 0.f;

#pragma unroll
    for (int kk = 0; kk < 4; kk++) {
        uint32_t ahi[2][4];
#pragma unroll
        for (int mt = 0; mt < 2; mt++) {
            uint32_t off = (uint32_t)((s0w + mt * 64 + (lane & 15)) * 144 +
                                      kk * 32 + (lane >> 4) * 16);
            ldm_x4(ahi[mt], s_xhi + off);
        }
        uint32_t bhi[4][4];
#pragma unroll
        for (int p = 0; p < 4; p++) {
            uint32_t off = (uint32_t)((o0w + p * 16 + (lane >> 4) * 8 + (lane & 7)) * 144 +
                                      kk * 32 + ((lane >> 3) & 1) * 16);
            ldm_x4(bhi[p], s_yhi + off);
        }
#pragma unroll
        for (int mt = 0; mt < 2; mt++)
#pragma unroll
            for (int nt = 0; nt < 8; nt++)
                mma_f16(acc[mt][nt], ahi[mt], &bhi[nt >> 1][(nt & 1) * 2]);
    }

    // epilogue: +bias -> out
#pragma unroll
    for (int mt = 0; mt < 2; mt++) {
        const int srow = s0 + s0w + mt * 64 + (lane >> 2);
#pragma unroll
        for (int nt = 0; nt < 8; nt++) {
            int o = o0w + nt * 8 + (lane & 3) * 2;
            float2 bb = *(float2*)&bias_s[o];
            float* p0 = out + ((size_t)b * NS + srow) * NO + o;
            *(float2*)p0 = make_float2(acc[mt][nt][0] + bb.x, acc[mt][nt][1] + bb.y);
            *(float2*)(p0 + 8 * NO) =
                make_float2(acc[mt][nt][2] + bb.x, acc[mt][nt][3] + bb.y);
        }
    }
}

// ===========================================================================
extern "C" void kernel_launch(void* const* d_in, const int* in_sizes, int n_in,
                              void* d_out, int out_size) {
    const float* x = nullptr;
    const float* W = nullptr;
    const float* bias = nullptr;
    for (int i = 0; i < n_in; i++) {
        if (in_sizes[i] == NB * NS * ND)      x = (const float*)d_in[i];
        else if (in_sizes[i] == NO * NS)      W = (const float*)d_in[i];
        else if (in_sizes[i] == NO)           bias = (const float*)d_in[i];
    }
    float* out = (float*)d_out;

    cudaFuncSetAttribute(g1, cudaFuncAttributeMaxDynamicSharedMemorySize, G1_SMEM);
    cudaFuncSetAttribute(g2, cudaFuncAttributeMaxDynamicSharedMemorySize, G2_SMEM);

    prep<<<576, 256>>>(x, W);
    g1<<<dim3(KSPLIT, NB), 256, G1_SMEM>>>();
    yred<<<(NB * NO * ND / 4) / 128, 128>>>();
    g2<<<dim3(NS / 128, NB), 256, G2_SMEM>>>(bias, out);
}